// round 2
// baseline (speedup 1.0000x reference)
#include <cuda_runtime.h>
#include <math.h>

#define Bn 8
#define Dc 6
#define NC 48
#define Hn 256
#define Wn 256
#define HW (Hn*Wn)       // 65536
#define H2n 128
#define HW2 (H2n*H2n)    // 16384

// ---------------- scratch (device globals; no allocation allowed) ----------------
__device__ float g_E  [Bn*HW];            // 2 MB
__device__ float g_te [Bn*10*HW];         // 20 MB
__device__ float g_h1 [Bn*NC*258*258];    // 97.5 MB
__device__ float g_h2 [Bn*NC*HW];         // 96 MB
__device__ float g_ch [Bn*HW2];           // CHANGE
__device__ float g_z  [Bn*NC*HW2];        // 25 MB (cm conv1 out, then bn+tanh in place)
__device__ float g_hcm[Bn*NC*130*130];    // 26 MB
__device__ float g_xm [Bn*Dc*HW2];
__device__ float g_red[276];   // [0..26] x moments | [42..137] h2 sum/sumsq | [138..233] z | [234..260] xm moments
__device__ float g_sb [384];   // ce[0..95] md[96..191] cm[192..287] bo[288..383] : scale then bias

__device__ const int c_dx[8] = {0,1,1,1,0,-1,-1,-1};
__device__ const int c_dy[8] = {1,1,0,-1,-1,-1,0,1};

__device__ __forceinline__ float ftanh(float x) {
    x = fminf(fmaxf(x, -15.f), 15.f);
    float e = __expf(2.f*x);
    return __fdividef(e - 1.f, e + 1.f);
}
__device__ __forceinline__ float fsig(float x) {
    return __fdividef(1.f, 1.f + __expf(-x));
}

// ---------------- tiny kernels ----------------
__global__ void k_zero(float* red) { if (threadIdx.x < 276) red[threadIdx.x] = 0.f; }

// first + second moments of a 6-channel field [B][6][hw]
__global__ void k_mom6(const float* __restrict__ x, float* __restrict__ out, int hw) {
    float S[6] = {0,0,0,0,0,0};
    float P[21];
    #pragma unroll
    for (int i = 0; i < 21; i++) P[i] = 0.f;
    int total = Bn*hw;
    for (int t = blockIdx.x*blockDim.x + threadIdx.x; t < total; t += gridDim.x*blockDim.x) {
        int b = t / hw, i = t - b*hw;
        const float* p = x + (long)b*6*hw + i;
        float v[6];
        #pragma unroll
        for (int d = 0; d < 6; d++) v[d] = p[(long)d*hw];
        int idx = 0;
        #pragma unroll
        for (int d = 0; d < 6; d++) {
            S[d] += v[d];
            #pragma unroll
            for (int e = d; e < 6; e++) { P[idx] += v[d]*v[e]; idx++; }
        }
    }
    #pragma unroll
    for (int o = 16; o > 0; o >>= 1) {
        #pragma unroll
        for (int d = 0; d < 6; d++)  S[d] += __shfl_down_sync(0xffffffffu, S[d], o);
        #pragma unroll
        for (int i = 0; i < 21; i++) P[i] += __shfl_down_sync(0xffffffffu, P[i], o);
    }
    if ((threadIdx.x & 31) == 0) {
        #pragma unroll
        for (int d = 0; d < 6; d++)  atomicAdd(&out[d], S[d]);
        #pragma unroll
        for (int i = 0; i < 21; i++) atomicAdd(&out[6+i], P[i]);
    }
}

// BN scale/bias for a 1x1 conv (48ch) derived from 6-ch input moments
__global__ void k_sb6(const float* __restrict__ mom, const float* __restrict__ w1,
                      const float* __restrict__ g, const float* __restrict__ bt,
                      float* __restrict__ sb, float invN) {
    int c = threadIdx.x;
    if (c >= NC) return;
    float m = 0.f;
    #pragma unroll
    for (int d = 0; d < 6; d++) m += w1[c*6+d]*mom[d];
    m *= invN;
    float q = 0.f; int idx = 0;
    #pragma unroll
    for (int d = 0; d < 6; d++)
        #pragma unroll
        for (int e = d; e < 6; e++) {
            float coef = (d == e) ? 1.f : 2.f;
            q += coef * w1[c*6+d]*w1[c*6+e]*mom[6+idx];
            idx++;
        }
    q *= invN;
    float var = q - m*m;
    float sc = g[c]*rsqrtf(var + 1e-5f);
    sb[c] = sc; sb[NC+c] = bt[c] - m*sc;
}

// BN scale/bias from direct per-channel sums
__global__ void k_bnsb(const float* __restrict__ sums, const float* __restrict__ g,
                       const float* __restrict__ bt, float* __restrict__ sb, float invN) {
    int c = threadIdx.x;
    if (c >= NC) return;
    float m = sums[c]*invN;
    float var = sums[NC+c]*invN - m*m;
    float sc = g[c]*rsqrtf(var + 1e-5f);
    sb[c] = sc; sb[NC+c] = bt[c] - m*sc;
}

// per-channel sum/sumsq reduction over [B][C][hw]
__global__ void k_cred(const float* __restrict__ d, float* __restrict__ sums, int C, int hw) {
    int c = blockIdx.y;
    float s = 0.f, q = 0.f;
    int total = Bn*hw;
    for (int t = blockIdx.x*blockDim.x + threadIdx.x; t < total; t += gridDim.x*blockDim.x) {
        int b = t / hw, i = t - b*hw;
        float v = d[((long)b*C + c)*hw + i];
        s += v; q = fmaf(v, v, q);
    }
    #pragma unroll
    for (int o = 16; o > 0; o >>= 1) {
        s += __shfl_down_sync(0xffffffffu, s, o);
        q += __shfl_down_sync(0xffffffffu, q, o);
    }
    __shared__ float ss[8], sq[8];
    int w = threadIdx.x >> 5, l = threadIdx.x & 31;
    if (l == 0) { ss[w] = s; sq[w] = q; }
    __syncthreads();
    if (threadIdx.x == 0) {
        float S = 0.f, Q = 0.f;
        for (int i = 0; i < 8; i++) { S += ss[i]; Q += sq[i]; }
        atomicAdd(&sums[c], S); atomicAdd(&sums[C+c], Q);
    }
}

// E field: compenv computed once (roll-equivariance: all 8 directions are shifts of E)
__global__ void k_env(const float* __restrict__ x, const float* __restrict__ w1,
                      const float* __restrict__ w2, const float* __restrict__ sb,
                      float* __restrict__ E) {
    __shared__ float s_w1[288], s_w2[48], s_s[48], s_b[48];
    int t = threadIdx.x;
    for (int i = t; i < 288; i += 256) s_w1[i] = w1[i];   // FIXED: full coverage
    if (t < 48) { s_w2[t] = w2[t]; s_s[t] = sb[t]; s_b[t] = sb[48+t]; }
    __syncthreads();
    int idx = blockIdx.x*256 + t;         // exactly Bn*HW threads
    int b = idx >> 16, pix = idx & 65535;
    const float* xp = x + (long)b*6*HW + pix;
    float v[6];
    #pragma unroll
    for (int d = 0; d < 6; d++) v[d] = xp[(long)d*HW];
    float e = 0.f;
    #pragma unroll 4
    for (int c = 0; c < 48; c++) {
        float y = s_w1[c*6]*v[0];
        #pragma unroll
        for (int d = 1; d < 6; d++) y = fmaf(s_w1[c*6+d], v[d], y);
        e = fmaf(s_w2[c], ftanh(fmaf(s_s[c], y, s_b[c])), e);
    }
    E[idx] = e;
}

// te = concat(x[:, :2], shifted E x8)  -> [B][10][256][256]
__global__ void k_te(const float* __restrict__ x, const float* __restrict__ E,
                     float* __restrict__ te) {
    int idx = blockIdx.x*256 + threadIdx.x;   // Bn*10*HW
    int b = idx / (10*HW); int r = idx - b*10*HW;
    int ch = r >> 16; int pix = r & 65535;
    float v;
    if (ch < 2) {
        v = x[((long)b*6 + ch)*HW + pix];
    } else {
        int k = ch - 2;
        int i = pix >> 8, j = pix & 255;
        int ii = (i + c_dy[k]) & 255;
        int jj = (j - c_dx[k]) & 255;
        v = E[b*HW + (ii << 8) + jj];
    }
    te[idx] = v;
}

// ---------------- generic direct 3x3 conv, grouped, optional pad & tanh ----------------
// 32x32 output tile per block, 256 threads, each thread 4 pixels x OCB channels.
template<int CIN_G, int OCB, int PAD, bool DOTANH>
__global__ void __launch_bounds__(256, 2)
k_conv3(const float* __restrict__ in, const float* __restrict__ wgt, float* __restrict__ out,
        int H_in, int W_in, int H_out, int W_out, int C_in, int C_out, int tilesX) {
    __shared__ float s_tile[34*34];
    __shared__ float s_w[CIN_G*9*OCB];
    int tid = threadIdx.x;
    int oc_base = blockIdx.x * OCB;
    int groups = C_in / CIN_G;
    int oc_per_group = C_out / groups;
    int ic_base = (oc_base / oc_per_group) * CIN_G;

    for (int i = tid; i < CIN_G*9*OCB; i += 256) {
        int o = i % OCB; int rest = i / OCB;   // rest = ic*9 + tap
        s_w[i] = wgt[(long)(oc_base + o)*(CIN_G*9) + rest];
    }

    int tX = blockIdx.y % tilesX, tY = blockIdx.y / tilesX;
    int ox0 = tX*32, oy0 = tY*32;
    int tx = tid & 31, ty = tid >> 5;

    float acc[4][OCB];
    #pragma unroll
    for (int p = 0; p < 4; p++)
        #pragma unroll
        for (int o = 0; o < OCB; o++) acc[p][o] = 0.f;

    const float* inb = in + ((long)blockIdx.z * C_in + ic_base) * H_in * W_in;

    for (int ic = 0; ic < CIN_G; ic++) {
        __syncthreads();
        const float* src = inb + (long)ic*H_in*W_in;
        for (int i = tid; i < 34*34; i += 256) {
            int ly = i / 34, lx = i - ly*34;
            int gy = oy0 - PAD + ly, gx = ox0 - PAD + lx;
            float v = 0.f;
            if ((unsigned)gy < (unsigned)H_in && (unsigned)gx < (unsigned)W_in)
                v = src[gy*W_in + gx];
            s_tile[i] = v;
        }
        __syncthreads();
        const float* wrow = &s_w[ic*9*OCB];
        #pragma unroll
        for (int tap = 0; tap < 9; tap++) {
            int ky = tap/3, kx = tap - ky*3;
            float w[OCB];
            #pragma unroll
            for (int o = 0; o < OCB; o++) w[o] = wrow[tap*OCB + o];
            #pragma unroll
            for (int p = 0; p < 4; p++) {
                float v = s_tile[(ty + 8*p + ky)*34 + tx + kx];
                #pragma unroll
                for (int o = 0; o < OCB; o++) acc[p][o] = fmaf(v, w[o], acc[p][o]);
            }
        }
    }

    #pragma unroll
    for (int p = 0; p < 4; p++) {
        int oy = oy0 + ty + 8*p, ox = ox0 + tx;
        if (oy < H_out && ox < W_out) {
            #pragma unroll
            for (int o = 0; o < OCB; o++) {
                float r = acc[p][o];
                if (DOTANH) r = ftanh(r);
                out[(((long)blockIdx.z*C_out + oc_base + o)*H_out + oy)*W_out + ox] = r;
            }
        }
    }
}

// CHANGE = sigmoid(conv2x2s2(tanh(bn(h2)), md_c2))
__global__ void k_change(const float* __restrict__ h2, const float* __restrict__ sb,
                         const float* __restrict__ w2, float* __restrict__ ch) {
    __shared__ float s_s[48], s_b[48], s_w[192];
    int t = threadIdx.x;
    if (t < 48) { s_s[t] = sb[t]; s_b[t] = sb[48+t]; }
    if (t < 192) s_w[t] = w2[t];
    __syncthreads();
    int idx = blockIdx.x*256 + t;             // Bn*HW2
    int b = idx >> 14, pix = idx & 16383;
    int i = pix >> 7, j = pix & 127;
    const float* hp0 = h2 + ((long)b*48)*HW + (2*i)*256 + 2*j;
    float a = 0.f;
    for (int c = 0; c < 48; c++) {
        const float* hp = hp0 + (long)c*HW;
        float s = s_s[c], bb = s_b[c];
        a = fmaf(ftanh(fmaf(s, hp[0],   bb)), s_w[c*4+0], a);
        a = fmaf(ftanh(fmaf(s, hp[1],   bb)), s_w[c*4+1], a);
        a = fmaf(ftanh(fmaf(s, hp[256], bb)), s_w[c*4+2], a);
        a = fmaf(ftanh(fmaf(s, hp[257], bb)), s_w[c*4+3], a);
    }
    ch[idx] = fsig(a);
}

// cm conv1: 2x2 stride2 grouped(3):  x[B,6,256,256] -> z[B,48,128,128]
__global__ void k_cm1(const float* __restrict__ x, const float* __restrict__ w,
                      float* __restrict__ z) {
    int idx = blockIdx.x*256 + threadIdx.x;   // Bn*48*HW2
    int b = idx / (48*HW2); int r = idx - b*48*HW2;
    int oc = r >> 14; int pix = r & 16383;
    int i = pix >> 7, j = pix & 127;
    int g = oc >> 4;
    const float* xp = x + ((long)b*6 + 2*g)*HW + (2*i)*256 + 2*j;
    const float* wp = w + oc*8;
    float a = wp[0]*xp[0] + wp[1]*xp[1] + wp[2]*xp[256] + wp[3]*xp[257]
            + wp[4]*xp[HW] + wp[5]*xp[HW+1] + wp[6]*xp[HW+256] + wp[7]*xp[HW+257];
    z[idx] = a;
}

// in-place tanh(bn(z))
__global__ void k_bntanh(float* __restrict__ z, const float* __restrict__ sb) {
    int idx = blockIdx.x*256 + threadIdx.x;
    int c = (idx >> 14) % 48;
    z[idx] = ftanh(fmaf(sb[c], z[idx], sb[48+c]));
}

// born + blend + head sigmoid
__global__ void k_final(const float* __restrict__ xm, const float* __restrict__ ch,
                        const float* __restrict__ w1, const float* __restrict__ w2,
                        const float* __restrict__ sb, float* __restrict__ out) {
    __shared__ float s_w1[288], s_w2[288], s_s[48], s_b[48];
    int t = threadIdx.x;
    for (int i = t; i < 288; i += 256) { s_w1[i] = w1[i]; s_w2[i] = w2[i]; }  // FIXED
    if (t < 48)  { s_s[t] = sb[t]; s_b[t] = sb[48+t]; }
    __syncthreads();
    int idx = blockIdx.x*256 + t;            // Bn*HW2
    int b = idx >> 14, pix = idx & 16383;
    const float* xp = xm + ((long)b*6)*HW2 + pix;
    float v[6];
    #pragma unroll
    for (int d = 0; d < 6; d++) v[d] = xp[d*HW2];
    float born[6] = {0,0,0,0,0,0};
    #pragma unroll 4
    for (int c = 0; c < 48; c++) {
        float y = s_w1[c*6]*v[0];
        #pragma unroll
        for (int d = 1; d < 6; d++) y = fmaf(s_w1[c*6+d], v[d], y);
        float h = ftanh(fmaf(s_s[c], y, s_b[c]));
        #pragma unroll
        for (int d = 0; d < 6; d++) born[d] = fmaf(s_w2[d*48+c], h, born[d]);
    }
    float cc = ch[idx];
    #pragma unroll
    for (int d = 0; d < 6; d++) {
        float o = v[d]*(1.f - cc) + cc*born[d];
        if (d < 3) o = fsig(o);
        out[((long)b*6 + d)*HW2 + pix] = o;
    }
}

// ---------------- launch ----------------
extern "C" void kernel_launch(void* const* d_in, const int* in_sizes, int n_in,
                              void* d_out, int out_size) {
    const float* x     = (const float*)d_in[0];
    const float* ce_w1 = (const float*)d_in[1];
    const float* ce_g  = (const float*)d_in[2];
    const float* ce_b  = (const float*)d_in[3];
    const float* ce_w2 = (const float*)d_in[4];
    const float* md_ct = (const float*)d_in[5];
    const float* md_c1 = (const float*)d_in[6];
    const float* md_g  = (const float*)d_in[7];
    const float* md_b  = (const float*)d_in[8];
    const float* md_c2 = (const float*)d_in[9];
    const float* cm_w1 = (const float*)d_in[10];
    const float* cm_g  = (const float*)d_in[11];
    const float* cm_b  = (const float*)d_in[12];
    const float* cm_ct = (const float*)d_in[13];
    const float* cm_c2 = (const float*)d_in[14];
    const float* bo_w1 = (const float*)d_in[15];
    const float* bo_g  = (const float*)d_in[16];
    const float* bo_b  = (const float*)d_in[17];
    const float* bo_w2 = (const float*)d_in[18];

    float *E, *te, *h1, *h2, *ch, *z, *hcm, *xm, *red, *sb;
    cudaGetSymbolAddress((void**)&E,   g_E);
    cudaGetSymbolAddress((void**)&te,  g_te);
    cudaGetSymbolAddress((void**)&h1,  g_h1);
    cudaGetSymbolAddress((void**)&h2,  g_h2);
    cudaGetSymbolAddress((void**)&ch,  g_ch);
    cudaGetSymbolAddress((void**)&z,   g_z);
    cudaGetSymbolAddress((void**)&hcm, g_hcm);
    cudaGetSymbolAddress((void**)&xm,  g_xm);
    cudaGetSymbolAddress((void**)&red, g_red);
    cudaGetSymbolAddress((void**)&sb,  g_sb);

    const float invN_full = 1.f/(float)(Bn*HW);    // 1/524288
    const float invN_half = 1.f/(float)(Bn*HW2);   // 1/131072

    k_zero<<<1, 512>>>(red);

    // ---- compenv (collapsed to one E field) ----
    k_mom6<<<64, 256>>>(x, red + 0, HW);
    k_sb6 <<<1, 64>>>(red + 0, ce_w1, ce_g, ce_b, sb + 0, invN_full);
    k_env <<<Bn*HW/256, 256>>>(x, ce_w1, ce_w2, sb + 0, E);
    k_te  <<<Bn*10*HW/256, 256>>>(x, E, te);

    // ---- merge change determinant ----
    k_conv3<10, 16, 2, true><<<dim3(3, 81, Bn), 256>>>(te, md_ct, h1, 256, 256, 258, 258, 10, 48, 9);
    k_conv3<48, 16, 0, true><<<dim3(3, 64, Bn), 256>>>(h1, md_c1, h2, 258, 258, 256, 256, 48, 48, 8);
    k_cred<<<dim3(32, 48), 256>>>(h2, red + 42, 48, HW);
    k_bnsb<<<1, 64>>>(red + 42, md_g, md_b, sb + 96, invN_full);
    k_change<<<Bn*HW2/256, 256>>>(h2, sb + 96, md_c2, ch);

    // ---- cell merge ----
    k_cm1<<<Bn*48*HW2/256, 256>>>(x, cm_w1, z);
    k_cred<<<dim3(8, 48), 256>>>(z, red + 138, 48, HW2);
    k_bnsb<<<1, 64>>>(red + 138, cm_g, cm_b, sb + 192, invN_half);
    k_bntanh<<<Bn*48*HW2/256, 256>>>(z, sb + 192);
    k_conv3<16, 16, 2, true><<<dim3(3, 25, Bn), 256>>>(z, cm_ct, hcm, 128, 128, 130, 130, 48, 48, 5);
    k_conv3<16, 2, 0, true><<<dim3(3, 16, Bn), 256>>>(hcm, cm_c2, xm, 130, 130, 128, 128, 48, 6, 4);

    // ---- born + blend ----
    k_mom6<<<64, 256>>>(xm, red + 234, HW2);
    k_sb6 <<<1, 64>>>(red + 234, bo_w1, bo_g, bo_b, sb + 288, invN_half);
    k_final<<<Bn*HW2/256, 256>>>(xm, ch, bo_w1, bo_w2, sb + 288, (float*)d_out);
}

// round 3
// speedup vs baseline: 1.7349x; 1.7349x over previous
#include <cuda_runtime.h>
#include <math.h>

#define Bn 8
#define Dc 6
#define NC 48
#define Hn 256
#define Wn 256
#define HW (Hn*Wn)       // 65536
#define H2n 128
#define HW2 (H2n*H2n)    // 16384

// ---------------- scratch ----------------
__device__ float g_E  [Bn*HW];            // 2 MB
__device__ float g_h1 [Bn*NC*258*258];    // 97.5 MB
__device__ float g_h2 [Bn*NC*HW];         // 96 MB
__device__ float g_ch [Bn*HW2];
__device__ float g_z  [Bn*NC*HW2];        // raw cm conv1 out (pre-BN)
__device__ float g_hcm[Bn*NC*130*130];
__device__ float g_xm [Bn*Dc*HW2];
__device__ float g_w5 [25*NC];            // folded 5x5 kernel on E, layout [tap][oc]
__device__ float g_red[276];   // [0..26] x mom | [42..137] h2 | [138..233] z | [234..260] xm mom
__device__ float g_sb [384];   // ce[0..95] md[96..191] cm[192..287] bo[288..383]

__device__ const int c_dx[8] = {0,1,1,1,0,-1,-1,-1};
__device__ const int c_dy[8] = {1,1,0,-1,-1,-1,0,1};

__device__ __forceinline__ float ftanh(float x) {
    x = fminf(fmaxf(x, -15.f), 15.f);
    float e = __expf(2.f*x);
    return __fdividef(e - 1.f, e + 1.f);
}
__device__ __forceinline__ float fsig(float x) {
    return __fdividef(1.f, 1.f + __expf(-x));
}

// ---------------- tiny kernels ----------------
__global__ void k_zero(float* red) { if (threadIdx.x < 276) red[threadIdx.x] = 0.f; }

__global__ void k_mom6(const float* __restrict__ x, float* __restrict__ out, int hw) {
    float S[6] = {0,0,0,0,0,0};
    float P[21];
    #pragma unroll
    for (int i = 0; i < 21; i++) P[i] = 0.f;
    int total = Bn*hw;
    for (int t = blockIdx.x*blockDim.x + threadIdx.x; t < total; t += gridDim.x*blockDim.x) {
        int b = t / hw, i = t - b*hw;
        const float* p = x + (long)b*6*hw + i;
        float v[6];
        #pragma unroll
        for (int d = 0; d < 6; d++) v[d] = p[(long)d*hw];
        int idx = 0;
        #pragma unroll
        for (int d = 0; d < 6; d++) {
            S[d] += v[d];
            #pragma unroll
            for (int e = d; e < 6; e++) { P[idx] += v[d]*v[e]; idx++; }
        }
    }
    #pragma unroll
    for (int o = 16; o > 0; o >>= 1) {
        #pragma unroll
        for (int d = 0; d < 6; d++)  S[d] += __shfl_down_sync(0xffffffffu, S[d], o);
        #pragma unroll
        for (int i = 0; i < 21; i++) P[i] += __shfl_down_sync(0xffffffffu, P[i], o);
    }
    if ((threadIdx.x & 31) == 0) {
        #pragma unroll
        for (int d = 0; d < 6; d++)  atomicAdd(&out[d], S[d]);
        #pragma unroll
        for (int i = 0; i < 21; i++) atomicAdd(&out[6+i], P[i]);
    }
}

__global__ void k_sb6(const float* __restrict__ mom, const float* __restrict__ w1,
                      const float* __restrict__ g, const float* __restrict__ bt,
                      float* __restrict__ sb, float invN) {
    int c = threadIdx.x;
    if (c >= NC) return;
    float m = 0.f;
    #pragma unroll
    for (int d = 0; d < 6; d++) m += w1[c*6+d]*mom[d];
    m *= invN;
    float q = 0.f; int idx = 0;
    #pragma unroll
    for (int d = 0; d < 6; d++)
        #pragma unroll
        for (int e = d; e < 6; e++) {
            float coef = (d == e) ? 1.f : 2.f;
            q += coef * w1[c*6+d]*w1[c*6+e]*mom[6+idx];
            idx++;
        }
    q *= invN;
    float var = q - m*m;
    float sc = g[c]*rsqrtf(var + 1e-5f);
    sb[c] = sc; sb[NC+c] = bt[c] - m*sc;
}

__global__ void k_bnsb(const float* __restrict__ sums, const float* __restrict__ g,
                       const float* __restrict__ bt, float* __restrict__ sb, float invN) {
    int c = threadIdx.x;
    if (c >= NC) return;
    float m = sums[c]*invN;
    float var = sums[NC+c]*invN - m*m;
    float sc = g[c]*rsqrtf(var + 1e-5f);
    sb[c] = sc; sb[NC+c] = bt[c] - m*sc;
}

// E field (compenv collapsed to one pass by roll-equivariance)
__global__ void k_env(const float* __restrict__ x, const float* __restrict__ w1,
                      const float* __restrict__ w2, const float* __restrict__ sb,
                      float* __restrict__ E) {
    __shared__ float s_w1[288], s_w2[48], s_s[48], s_b[48];
    int t = threadIdx.x;
    for (int i = t; i < 288; i += 256) s_w1[i] = w1[i];
    if (t < 48) { s_w2[t] = w2[t]; s_s[t] = sb[t]; s_b[t] = sb[48+t]; }
    __syncthreads();
    int idx = blockIdx.x*256 + t;
    int b = idx >> 16, pix = idx & 65535;
    const float* xp = x + (long)b*6*HW + pix;
    float v[6];
    #pragma unroll
    for (int d = 0; d < 6; d++) v[d] = xp[(long)d*HW];
    float e = 0.f;
    #pragma unroll 4
    for (int c = 0; c < 48; c++) {
        float y = s_w1[c*6]*v[0];
        #pragma unroll
        for (int d = 1; d < 6; d++) y = fmaf(s_w1[c*6+d], v[d], y);
        e = fmaf(s_w2[c], ftanh(fmaf(s_s[c], y, s_b[c])), e);
    }
    E[idx] = e;
}

// build folded 5x5 kernel: W5[(u*5+v)*48+oc] = sum of shifted 3x3 taps
__global__ void k_w5(const float* __restrict__ md_ct, float* __restrict__ W5) {
    int oc = threadIdx.x;
    if (oc >= 48) return;
    float w5[25];
    #pragma unroll
    for (int i = 0; i < 25; i++) w5[i] = 0.f;
    for (int k = 0; k < 8; k++)
        for (int ky = 0; ky < 3; ky++)
            for (int kx = 0; kx < 3; kx++) {
                int u = ky - 2 + c_dy[k] + 3;
                int v = kx - 2 - c_dx[k] + 3;
                w5[u*5+v] += md_ct[oc*90 + (k+2)*9 + ky*3 + kx];
            }
    for (int i = 0; i < 25; i++) W5[i*48 + oc] = w5[i];
}

// md_ct interior: h1[p,q] for p,q in [2,255] = 5x5(E_circ) + 2x 3x3(x), then tanh
__global__ void __launch_bounds__(256, 2)
k_mdct(const float* __restrict__ x, const float* __restrict__ E,
       const float* __restrict__ W5, const float* __restrict__ md_ct,
       float* __restrict__ h1) {
    __shared__ float sE[36*36];
    __shared__ float sx[2][34*34];
    __shared__ float s_w5[25*16];
    __shared__ float s_w3[2*9*16];
    int tid = threadIdx.x;
    int oc_base = blockIdx.x * 16;
    int b = blockIdx.z;
    int tX = blockIdx.y & 7, tY = blockIdx.y >> 3;
    int p0 = 2 + tY*32, q0 = 2 + tX*32;

    for (int i = tid; i < 25*16; i += 256) {
        int tap = i >> 4, o = i & 15;
        s_w5[i] = W5[tap*48 + oc_base + o];
    }
    for (int i = tid; i < 288; i += 256) {
        int o = i & 15, rest = i >> 4;       // rest = ch*9+tap
        s_w3[i] = md_ct[(oc_base + o)*90 + rest];
    }
    for (int i = tid; i < 1296; i += 256) {
        int lr = i / 36, lc = i - lr*36;
        int gy = (p0 - 3 + lr) & 255, gx = (q0 - 3 + lc) & 255;
        sE[i] = E[b*HW + (gy << 8) + gx];
    }
    #pragma unroll
    for (int ch = 0; ch < 2; ch++)
        for (int i = tid; i < 1156; i += 256) {
            int lr = i / 34, lc = i - lr*34;
            int gy = p0 - 2 + lr, gx = q0 - 2 + lc;
            float v = 0.f;
            if (gy < 256 && gx < 256) v = x[((long)b*6 + ch)*HW + (gy << 8) + gx];
            sx[ch][i] = v;
        }
    __syncthreads();

    int tx = tid & 31, ty = tid >> 5;
    float acc[4][16];
    #pragma unroll
    for (int p = 0; p < 4; p++)
        #pragma unroll
        for (int o = 0; o < 16; o++) acc[p][o] = 0.f;

    // 5x5 on E
    #pragma unroll
    for (int u = 0; u < 5; u++) {
        float v[4][5];
        #pragma unroll
        for (int p = 0; p < 4; p++) {
            int base = (ty + 8*p + u)*36 + tx;
            #pragma unroll
            for (int j = 0; j < 5; j++) v[p][j] = sE[base + j];
        }
        #pragma unroll
        for (int vv = 0; vv < 5; vv++) {
            const float4* w4 = (const float4*)&s_w5[(u*5 + vv)*16];
            float w[16];
            #pragma unroll
            for (int q = 0; q < 4; q++) {
                float4 t4 = w4[q];
                w[q*4] = t4.x; w[q*4+1] = t4.y; w[q*4+2] = t4.z; w[q*4+3] = t4.w;
            }
            #pragma unroll
            for (int p = 0; p < 4; p++)
                #pragma unroll
                for (int o = 0; o < 16; o++)
                    acc[p][o] = fmaf(v[p][vv], w[o], acc[p][o]);
        }
    }
    // 3x3 on x0,x1
    #pragma unroll
    for (int ch = 0; ch < 2; ch++)
        #pragma unroll
        for (int ky = 0; ky < 3; ky++) {
            float v[4][3];
            #pragma unroll
            for (int p = 0; p < 4; p++) {
                int base = (ty + 8*p + ky)*34 + tx;
                v[p][0] = sx[ch][base]; v[p][1] = sx[ch][base+1]; v[p][2] = sx[ch][base+2];
            }
            #pragma unroll
            for (int kx = 0; kx < 3; kx++) {
                const float4* w4 = (const float4*)&s_w3[(ch*9 + ky*3 + kx)*16];
                float w[16];
                #pragma unroll
                for (int q = 0; q < 4; q++) {
                    float4 t4 = w4[q];
                    w[q*4] = t4.x; w[q*4+1] = t4.y; w[q*4+2] = t4.z; w[q*4+3] = t4.w;
                }
                #pragma unroll
                for (int p = 0; p < 4; p++)
                    #pragma unroll
                    for (int o = 0; o < 16; o++)
                        acc[p][o] = fmaf(v[p][kx], w[o], acc[p][o]);
            }
        }

    #pragma unroll
    for (int p = 0; p < 4; p++) {
        int pp = p0 + ty + 8*p, qq = q0 + tx;
        if (pp <= 255 && qq <= 255) {
            #pragma unroll
            for (int o = 0; o < 16; o++)
                h1[(((long)b*48 + oc_base + o)*258 + pp)*258 + qq] = ftanh(acc[p][o]);
        }
    }
}

// md_ct boundary: exact per-channel loop with zero-pad masks
__global__ void k_mdct_edge(const float* __restrict__ x, const float* __restrict__ E,
                            const float* __restrict__ md_ct, float* __restrict__ h1) {
    __shared__ float s_w[4320];     // [ch*9+tap][48]
    int tid = threadIdx.x;
    for (int i = tid; i < 4320; i += 256) {
        int oc = i % 48, rest = i / 48;
        s_w[rest*48 + oc] = md_ct[oc*90 + rest];
    }
    __syncthreads();
    int idx = blockIdx.x*256 + tid;       // [0,2048)
    int b = blockIdx.y;
    int p, q;
    if (idx < 1032) { int r = idx/258; p = (r < 2) ? r : 254 + r; q = idx - r*258; }
    else { int j = idx - 1032; int c = j/254; q = (c < 2) ? c : 254 + c; p = 2 + (j - c*254); }
    float acc[48];
    #pragma unroll
    for (int o = 0; o < 48; o++) acc[o] = 0.f;
    for (int ch = 0; ch < 10; ch++)
        for (int ky = 0; ky < 3; ky++)
            for (int kx = 0; kx < 3; kx++) {
                int y = p - 2 + ky, xx = q - 2 + kx;
                if ((unsigned)y < 256u && (unsigned)xx < 256u) {
                    float v;
                    if (ch < 2) v = x[((long)b*6 + ch)*HW + (y << 8) + xx];
                    else {
                        int k = ch - 2;
                        v = E[b*HW + (((y + c_dy[k]) & 255) << 8) + ((xx - c_dx[k]) & 255)];
                    }
                    const float* wr = &s_w[(ch*9 + ky*3 + kx)*48];
                    #pragma unroll
                    for (int o = 0; o < 48; o++) acc[o] = fmaf(v, wr[o], acc[o]);
                }
            }
    for (int o = 0; o < 48; o++)
        h1[(((long)b*48 + o)*258 + p)*258 + q] = ftanh(acc[o]);
}

// ---------------- optimized direct 3x3 conv ----------------
template<int CIN_G, int OCB, int PAD, bool DOTANH, bool SAFE, bool PREBN, bool REDUCE>
__global__ void __launch_bounds__(256, 2)
k_conv3(const float* __restrict__ in, const float* __restrict__ wgt,
        const float* __restrict__ sbp, float* __restrict__ out, float* __restrict__ red,
        int H_in, int W_in, int H_out, int W_out, int C_in, int C_out, int tilesX) {
    __shared__ float s_tile[34*34];
    __shared__ float s_w[CIN_G*9*OCB];
    __shared__ float s_sc[CIN_G], s_bi[CIN_G];
    __shared__ float s_rs[8][16], s_rq[8][16];

    int tid = threadIdx.x;
    int oc_base = blockIdx.x * OCB;
    int groups = C_in / CIN_G;
    int oc_per_group = C_out / groups;
    int ic_base = (oc_base / oc_per_group) * CIN_G;

    for (int i = tid; i < CIN_G*9*OCB; i += 256) {
        int o = i % OCB, rest = i / OCB;
        s_w[i] = wgt[(long)(oc_base + o)*(CIN_G*9) + rest];
    }
    if (PREBN && tid < CIN_G) { s_sc[tid] = sbp[ic_base + tid]; s_bi[tid] = sbp[48 + ic_base + tid]; }

    int tX = blockIdx.y % tilesX, tY = blockIdx.y / tilesX;
    int ox0 = tX*32, oy0 = tY*32;
    int tx = tid & 31, ty = tid >> 5;

    // per-thread load slots (computed once)
    int off[5]; bool vld[5];
    #pragma unroll
    for (int s = 0; s < 5; s++) {
        int j = tid + s*256;
        int ly = j / 34, lx = j - ly*34;
        int gy = oy0 - PAD + ly, gx = ox0 - PAD + lx;
        bool v = (j < 1156);
        if (SAFE) v = v && ((unsigned)gy < (unsigned)H_in) && ((unsigned)gx < (unsigned)W_in);
        vld[s] = v;
        off[s] = gy*W_in + gx;
    }

    const float* inb = in + ((long)blockIdx.z * C_in + ic_base) * H_in * W_in;
    float r[5];
    #pragma unroll
    for (int s = 0; s < 5; s++) r[s] = vld[s] ? __ldg(inb + off[s]) : 0.f;

    float acc[4][OCB];
    #pragma unroll
    for (int p = 0; p < 4; p++)
        #pragma unroll
        for (int o = 0; o < OCB; o++) acc[p][o] = 0.f;

    __syncthreads();

    #pragma unroll 1
    for (int ic = 0; ic < CIN_G; ic++) {
        float sc = 0.f, bi = 0.f;
        if (PREBN) { sc = s_sc[ic]; bi = s_bi[ic]; }
        #pragma unroll
        for (int s = 0; s < 5; s++) {
            int j = tid + s*256;
            if (j < 1156) {
                float v = r[s];
                if (PREBN) v = ftanh(fmaf(sc, v, bi));
                s_tile[j] = v;
            }
        }
        __syncthreads();
        if (ic + 1 < CIN_G) {
            const float* src = inb + (long)(ic+1)*H_in*W_in;
            #pragma unroll
            for (int s = 0; s < 5; s++) r[s] = vld[s] ? __ldg(src + off[s]) : 0.f;
        }
        const float* wic = &s_w[ic*9*OCB];
        #pragma unroll
        for (int ky = 0; ky < 3; ky++) {
            float v[4][3];
            #pragma unroll
            for (int p = 0; p < 4; p++) {
                int base = (ty + 8*p + ky)*34 + tx;
                v[p][0] = s_tile[base]; v[p][1] = s_tile[base+1]; v[p][2] = s_tile[base+2];
            }
            #pragma unroll
            for (int kx = 0; kx < 3; kx++) {
                float w[OCB];
                if (OCB % 4 == 0) {
                    const float4* w4 = (const float4*)&wic[(ky*3 + kx)*OCB];
                    #pragma unroll
                    for (int q = 0; q < OCB/4; q++) {
                        float4 t4 = w4[q];
                        w[q*4] = t4.x; w[q*4+1] = t4.y; w[q*4+2] = t4.z; w[q*4+3] = t4.w;
                    }
                } else {
                    #pragma unroll
                    for (int o = 0; o < OCB; o++) w[o] = wic[(ky*3 + kx)*OCB + o];
                }
                #pragma unroll
                for (int p = 0; p < 4; p++)
                    #pragma unroll
                    for (int o = 0; o < OCB; o++)
                        acc[p][o] = fmaf(v[p][kx], w[o], acc[p][o]);
            }
        }
        __syncthreads();
    }

    #pragma unroll
    for (int p = 0; p < 4; p++) {
        int oy = oy0 + ty + 8*p, ox = ox0 + tx;
        bool ok = (oy < H_out) && (ox < W_out);
        #pragma unroll
        for (int o = 0; o < OCB; o++) {
            float val = acc[p][o];
            if (DOTANH) val = ftanh(val);
            if (ok) out[(((long)blockIdx.z*C_out + oc_base + o)*H_out + oy)*W_out + ox] = val;
            if (REDUCE) acc[p][o] = ok ? val : 0.f;
        }
    }

    if (REDUCE) {
        int lane = tid & 31, warp = tid >> 5;
        #pragma unroll
        for (int o = 0; o < OCB; o++) {
            float s = acc[0][o] + acc[1][o] + acc[2][o] + acc[3][o];
            float q = acc[0][o]*acc[0][o] + acc[1][o]*acc[1][o]
                    + acc[2][o]*acc[2][o] + acc[3][o]*acc[3][o];
            #pragma unroll
            for (int d = 16; d > 0; d >>= 1) {
                s += __shfl_down_sync(0xffffffffu, s, d);
                q += __shfl_down_sync(0xffffffffu, q, d);
            }
            if (lane == 0) { s_rs[warp][o] = s; s_rq[warp][o] = q; }
        }
        __syncthreads();
        if (tid < OCB) {
            float S = 0.f, Q = 0.f;
            #pragma unroll
            for (int w8 = 0; w8 < 8; w8++) { S += s_rs[w8][tid]; Q += s_rq[w8][tid]; }
            atomicAdd(&red[oc_base + tid], S);
            atomicAdd(&red[C_out + oc_base + tid], Q);
        }
    }
}

// CHANGE = sigmoid(conv2x2s2(tanh(bn(h2)), md_c2))
__global__ void k_change(const float* __restrict__ h2, const float* __restrict__ sb,
                         const float* __restrict__ w2, float* __restrict__ ch) {
    __shared__ float s_s[48], s_b[48], s_w[192];
    int t = threadIdx.x;
    if (t < 48) { s_s[t] = sb[t]; s_b[t] = sb[48+t]; }
    if (t < 192) s_w[t] = w2[t];
    __syncthreads();
    int idx = blockIdx.x*256 + t;
    int b = idx >> 14, pix = idx & 16383;
    int i = pix >> 7, j = pix & 127;
    const float* hp0 = h2 + ((long)b*48)*HW + (2*i)*256 + 2*j;
    float a = 0.f;
    for (int c = 0; c < 48; c++) {
        const float* hp = hp0 + (long)c*HW;
        float s = s_s[c], bb = s_b[c];
        a = fmaf(ftanh(fmaf(s, hp[0],   bb)), s_w[c*4+0], a);
        a = fmaf(ftanh(fmaf(s, hp[1],   bb)), s_w[c*4+1], a);
        a = fmaf(ftanh(fmaf(s, hp[256], bb)), s_w[c*4+2], a);
        a = fmaf(ftanh(fmaf(s, hp[257], bb)), s_w[c*4+3], a);
    }
    ch[idx] = fsig(a);
}

// cm conv1 (2x2 s2 g3) fused with per-channel sum/sumsq reduction
__global__ void k_cm1red(const float* __restrict__ x, const float* __restrict__ w,
                         float* __restrict__ z, float* __restrict__ red) {
    __shared__ float ss[8], sq[8];
    int tid = threadIdx.x;
    int idx = blockIdx.x*256 + tid;
    int b = idx / (48*HW2); int r = idx - b*48*HW2;
    int oc = r >> 14; int pix = r & 16383;
    int i = pix >> 7, j = pix & 127;
    int g = oc >> 4;
    const float* xp = x + ((long)b*6 + 2*g)*HW + (2*i)*256 + 2*j;
    const float* wp = w + oc*8;
    float a = wp[0]*xp[0] + wp[1]*xp[1] + wp[2]*xp[256] + wp[3]*xp[257]
            + wp[4]*xp[HW] + wp[5]*xp[HW+1] + wp[6]*xp[HW+256] + wp[7]*xp[HW+257];
    z[idx] = a;
    float s = a, q = a*a;
    #pragma unroll
    for (int d = 16; d > 0; d >>= 1) {
        s += __shfl_down_sync(0xffffffffu, s, d);
        q += __shfl_down_sync(0xffffffffu, q, d);
    }
    int warp = tid >> 5, lane = tid & 31;
    if (lane == 0) { ss[warp] = s; sq[warp] = q; }
    __syncthreads();
    if (tid == 0) {
        float S = 0.f, Q = 0.f;
        #pragma unroll
        for (int w8 = 0; w8 < 8; w8++) { S += ss[w8]; Q += sq[w8]; }
        atomicAdd(&red[oc], S); atomicAdd(&red[48 + oc], Q);
    }
}

// born + blend + head sigmoid
__global__ void k_final(const float* __restrict__ xm, const float* __restrict__ ch,
                        const float* __restrict__ w1, const float* __restrict__ w2,
                        const float* __restrict__ sb, float* __restrict__ out) {
    __shared__ float s_w1[288], s_w2[288], s_s[48], s_b[48];
    int t = threadIdx.x;
    for (int i = t; i < 288; i += 256) { s_w1[i] = w1[i]; s_w2[i] = w2[i]; }
    if (t < 48)  { s_s[t] = sb[t]; s_b[t] = sb[48+t]; }
    __syncthreads();
    int idx = blockIdx.x*256 + t;
    int b = idx >> 14, pix = idx & 16383;
    const float* xp = xm + ((long)b*6)*HW2 + pix;
    float v[6];
    #pragma unroll
    for (int d = 0; d < 6; d++) v[d] = xp[d*HW2];
    float born[6] = {0,0,0,0,0,0};
    #pragma unroll 4
    for (int c = 0; c < 48; c++) {
        float y = s_w1[c*6]*v[0];
        #pragma unroll
        for (int d = 1; d < 6; d++) y = fmaf(s_w1[c*6+d], v[d], y);
        float h = ftanh(fmaf(s_s[c], y, s_b[c]));
        #pragma unroll
        for (int d = 0; d < 6; d++) born[d] = fmaf(s_w2[d*48+c], h, born[d]);
    }
    float cc = ch[idx];
    #pragma unroll
    for (int d = 0; d < 6; d++) {
        float o = v[d]*(1.f - cc) + cc*born[d];
        if (d < 3) o = fsig(o);
        out[((long)b*6 + d)*HW2 + pix] = o;
    }
}

// ---------------- launch ----------------
extern "C" void kernel_launch(void* const* d_in, const int* in_sizes, int n_in,
                              void* d_out, int out_size) {
    const float* x     = (const float*)d_in[0];
    const float* ce_w1 = (const float*)d_in[1];
    const float* ce_g  = (const float*)d_in[2];
    const float* ce_b  = (const float*)d_in[3];
    const float* ce_w2 = (const float*)d_in[4];
    const float* md_ct = (const float*)d_in[5];
    const float* md_c1 = (const float*)d_in[6];
    const float* md_g  = (const float*)d_in[7];
    const float* md_b  = (const float*)d_in[8];
    const float* md_c2 = (const float*)d_in[9];
    const float* cm_w1 = (const float*)d_in[10];
    const float* cm_g  = (const float*)d_in[11];
    const float* cm_b  = (const float*)d_in[12];
    const float* cm_ct = (const float*)d_in[13];
    const float* cm_c2 = (const float*)d_in[14];
    const float* bo_w1 = (const float*)d_in[15];
    const float* bo_g  = (const float*)d_in[16];
    const float* bo_b  = (const float*)d_in[17];
    const float* bo_w2 = (const float*)d_in[18];

    float *E, *h1, *h2, *ch, *z, *hcm, *xm, *w5, *red, *sb;
    cudaGetSymbolAddress((void**)&E,   g_E);
    cudaGetSymbolAddress((void**)&h1,  g_h1);
    cudaGetSymbolAddress((void**)&h2,  g_h2);
    cudaGetSymbolAddress((void**)&ch,  g_ch);
    cudaGetSymbolAddress((void**)&z,   g_z);
    cudaGetSymbolAddress((void**)&hcm, g_hcm);
    cudaGetSymbolAddress((void**)&xm,  g_xm);
    cudaGetSymbolAddress((void**)&w5,  g_w5);
    cudaGetSymbolAddress((void**)&red, g_red);
    cudaGetSymbolAddress((void**)&sb,  g_sb);

    const float invN_full = 1.f/(float)(Bn*HW);
    const float invN_half = 1.f/(float)(Bn*HW2);

    k_zero<<<1, 512>>>(red);

    // ---- compenv ----
    k_mom6<<<64, 256>>>(x, red + 0, HW);
    k_sb6 <<<1, 64>>>(red + 0, ce_w1, ce_g, ce_b, sb + 0, invN_full);
    k_env <<<Bn*HW/256, 256>>>(x, ce_w1, ce_w2, sb + 0, E);

    // ---- merge change determinant ----
    k_w5<<<1, 64>>>(md_ct, w5);
    k_mdct<<<dim3(3, 64, Bn), 256>>>(x, E, w5, md_ct, h1);
    k_mdct_edge<<<dim3(8, Bn), 256>>>(x, E, md_ct, h1);
    k_conv3<48, 16, 0, true, false, false, true>
        <<<dim3(3, 64, Bn), 256>>>(h1, md_c1, nullptr, h2, red + 42,
                                   258, 258, 256, 256, 48, 48, 8);
    k_bnsb<<<1, 64>>>(red + 42, md_g, md_b, sb + 96, invN_full);
    k_change<<<Bn*HW2/256, 256>>>(h2, sb + 96, md_c2, ch);

    // ---- cell merge ----
    k_cm1red<<<Bn*48*HW2/256, 256>>>(x, cm_w1, z, red + 138);
    k_bnsb<<<1, 64>>>(red + 138, cm_g, cm_b, sb + 192, invN_half);
    k_conv3<16, 16, 2, true, true, true, false>
        <<<dim3(3, 25, Bn), 256>>>(z, cm_ct, sb + 192, hcm, nullptr,
                                   128, 128, 130, 130, 48, 48, 5);
    k_conv3<16, 2, 0, true, false, false, false>
        <<<dim3(3, 16, Bn), 256>>>(hcm, cm_c2, nullptr, xm, nullptr,
                                   130, 130, 128, 128, 48, 6, 4);

    // ---- born + blend ----
    k_mom6<<<64, 256>>>(xm, red + 234, HW2);
    k_sb6 <<<1, 64>>>(red + 234, bo_w1, bo_g, bo_b, sb + 288, invN_half);
    k_final<<<Bn*HW2/256, 256>>>(xm, ch, bo_w1, bo_w2, sb + 288, (float*)d_out);
}

// round 4
// speedup vs baseline: 1.8834x; 1.0856x over previous
#include <cuda_runtime.h>
#include <math.h>

#define Bn 8
#define Dc 6
#define NC 48
#define Hn 256
#define Wn 256
#define HW (Hn*Wn)       // 65536
#define H2n 128
#define HW2 (H2n*H2n)    // 16384

// ---------------- scratch ----------------
__device__ float g_E  [Bn*HW];
__device__ float g_h1 [Bn*NC*258*258];
__device__ float g_h2 [Bn*NC*HW];
__device__ float g_ch [Bn*HW2];
__device__ float g_z  [Bn*NC*HW2];
__device__ float g_hcm[Bn*NC*130*130];
__device__ float g_xm [Bn*Dc*HW2];
__device__ float g_w5 [25*NC];
__device__ float g_red[276];
__device__ float g_sb [384];

__device__ const int c_dx[8] = {0,1,1,1,0,-1,-1,-1};
__device__ const int c_dy[8] = {1,1,0,-1,-1,-1,0,1};

__device__ __forceinline__ float ftanh(float x) {
    x = fminf(fmaxf(x, -15.f), 15.f);
    float e = __expf(2.f*x);
    return __fdividef(e - 1.f, e + 1.f);
}
__device__ __forceinline__ float fsig(float x) {
    return __fdividef(1.f, 1.f + __expf(-x));
}

// ---- packed f32x2 helpers (Blackwell FFMA2 — ptxas never emits this from C++) ----
__device__ __forceinline__ unsigned long long pack2(float a, float b) {
    unsigned long long r;
    asm("mov.b64 %0, {%1, %2};" : "=l"(r) : "f"(a), "f"(b));
    return r;
}
__device__ __forceinline__ void ffma2(unsigned long long &d, unsigned long long a,
                                      unsigned long long b) {
    asm("fma.rn.f32x2 %0, %1, %2, %0;" : "+l"(d) : "l"(a), "l"(b));
}
__device__ __forceinline__ float2 unpack2(unsigned long long v) {
    float2 f;
    asm("mov.b64 {%0, %1}, %2;" : "=f"(f.x), "=f"(f.y) : "l"(v));
    return f;
}

// ---------------- tiny kernels ----------------
__global__ void k_zero(float* red) { if (threadIdx.x < 276) red[threadIdx.x] = 0.f; }

__global__ void k_mom6(const float* __restrict__ x, float* __restrict__ out, int hw) {
    float S[6] = {0,0,0,0,0,0};
    float P[21];
    #pragma unroll
    for (int i = 0; i < 21; i++) P[i] = 0.f;
    int total = Bn*hw;
    for (int t = blockIdx.x*blockDim.x + threadIdx.x; t < total; t += gridDim.x*blockDim.x) {
        int b = t / hw, i = t - b*hw;
        const float* p = x + (long)b*6*hw + i;
        float v[6];
        #pragma unroll
        for (int d = 0; d < 6; d++) v[d] = p[(long)d*hw];
        int idx = 0;
        #pragma unroll
        for (int d = 0; d < 6; d++) {
            S[d] += v[d];
            #pragma unroll
            for (int e = d; e < 6; e++) { P[idx] += v[d]*v[e]; idx++; }
        }
    }
    #pragma unroll
    for (int o = 16; o > 0; o >>= 1) {
        #pragma unroll
        for (int d = 0; d < 6; d++)  S[d] += __shfl_down_sync(0xffffffffu, S[d], o);
        #pragma unroll
        for (int i = 0; i < 21; i++) P[i] += __shfl_down_sync(0xffffffffu, P[i], o);
    }
    if ((threadIdx.x & 31) == 0) {
        #pragma unroll
        for (int d = 0; d < 6; d++)  atomicAdd(&out[d], S[d]);
        #pragma unroll
        for (int i = 0; i < 21; i++) atomicAdd(&out[6+i], P[i]);
    }
}

__global__ void k_sb6(const float* __restrict__ mom, const float* __restrict__ w1,
                      const float* __restrict__ g, const float* __restrict__ bt,
                      float* __restrict__ sb, float invN) {
    int c = threadIdx.x;
    if (c >= NC) return;
    float m = 0.f;
    #pragma unroll
    for (int d = 0; d < 6; d++) m += w1[c*6+d]*mom[d];
    m *= invN;
    float q = 0.f; int idx = 0;
    #pragma unroll
    for (int d = 0; d < 6; d++)
        #pragma unroll
        for (int e = d; e < 6; e++) {
            float coef = (d == e) ? 1.f : 2.f;
            q += coef * w1[c*6+d]*w1[c*6+e]*mom[6+idx];
            idx++;
        }
    q *= invN;
    float var = q - m*m;
    float sc = g[c]*rsqrtf(var + 1e-5f);
    sb[c] = sc; sb[NC+c] = bt[c] - m*sc;
}

__global__ void k_bnsb(const float* __restrict__ sums, const float* __restrict__ g,
                       const float* __restrict__ bt, float* __restrict__ sb, float invN) {
    int c = threadIdx.x;
    if (c >= NC) return;
    float m = sums[c]*invN;
    float var = sums[NC+c]*invN - m*m;
    float sc = g[c]*rsqrtf(var + 1e-5f);
    sb[c] = sc; sb[NC+c] = bt[c] - m*sc;
}

__global__ void k_env(const float* __restrict__ x, const float* __restrict__ w1,
                      const float* __restrict__ w2, const float* __restrict__ sb,
                      float* __restrict__ E) {
    __shared__ float s_w1[288], s_w2[48], s_s[48], s_b[48];
    int t = threadIdx.x;
    for (int i = t; i < 288; i += 256) s_w1[i] = w1[i];
    if (t < 48) { s_w2[t] = w2[t]; s_s[t] = sb[t]; s_b[t] = sb[48+t]; }
    __syncthreads();
    int idx = blockIdx.x*256 + t;
    int b = idx >> 16, pix = idx & 65535;
    const float* xp = x + (long)b*6*HW + pix;
    float v[6];
    #pragma unroll
    for (int d = 0; d < 6; d++) v[d] = xp[(long)d*HW];
    float e = 0.f;
    #pragma unroll 4
    for (int c = 0; c < 48; c++) {
        float y = s_w1[c*6]*v[0];
        #pragma unroll
        for (int d = 1; d < 6; d++) y = fmaf(s_w1[c*6+d], v[d], y);
        e = fmaf(s_w2[c], ftanh(fmaf(s_s[c], y, s_b[c])), e);
    }
    E[idx] = e;
}

__global__ void k_w5(const float* __restrict__ md_ct, float* __restrict__ W5) {
    int oc = threadIdx.x;
    if (oc >= 48) return;
    float w5[25];
    #pragma unroll
    for (int i = 0; i < 25; i++) w5[i] = 0.f;
    for (int k = 0; k < 8; k++)
        for (int ky = 0; ky < 3; ky++)
            for (int kx = 0; kx < 3; kx++) {
                int u = ky - 2 + c_dy[k] + 3;
                int v = kx - 2 - c_dx[k] + 3;
                w5[u*5+v] += md_ct[oc*90 + (k+2)*9 + ky*3 + kx];
            }
    for (int i = 0; i < 25; i++) W5[i*48 + oc] = w5[i];
}

// md_ct interior, packed FFMA2 over oc pairs
__global__ void __launch_bounds__(256, 2)
k_mdct(const float* __restrict__ x, const float* __restrict__ E,
       const float* __restrict__ W5, const float* __restrict__ md_ct,
       float* __restrict__ h1) {
    __shared__ float sE[36*36];
    __shared__ float sx[2][34*34];
    __shared__ alignas(16) float s_w5[25*16];
    __shared__ alignas(16) float s_w3[2*9*16];
    int tid = threadIdx.x;
    int oc_base = blockIdx.x * 16;
    int b = blockIdx.z;
    int tX = blockIdx.y & 7, tY = blockIdx.y >> 3;
    int p0 = 2 + tY*32, q0 = 2 + tX*32;

    for (int i = tid; i < 25*16; i += 256) {
        int tap = i >> 4, o = i & 15;
        s_w5[i] = W5[tap*48 + oc_base + o];
    }
    for (int i = tid; i < 288; i += 256) {
        int o = i & 15, rest = i >> 4;
        s_w3[i] = md_ct[(oc_base + o)*90 + rest];
    }
    for (int i = tid; i < 1296; i += 256) {
        int lr = i / 36, lc = i - lr*36;
        int gy = (p0 - 3 + lr) & 255, gx = (q0 - 3 + lc) & 255;
        sE[i] = E[b*HW + (gy << 8) + gx];
    }
    #pragma unroll
    for (int ch = 0; ch < 2; ch++)
        for (int i = tid; i < 1156; i += 256) {
            int lr = i / 34, lc = i - lr*34;
            int gy = p0 - 2 + lr, gx = q0 - 2 + lc;
            float v = 0.f;
            if (gy < 256 && gx < 256) v = x[((long)b*6 + ch)*HW + (gy << 8) + gx];
            sx[ch][i] = v;
        }
    __syncthreads();

    int tx = tid & 31, ty = tid >> 5;
    unsigned long long acc2[4][8];
    #pragma unroll
    for (int p = 0; p < 4; p++)
        #pragma unroll
        for (int j = 0; j < 8; j++) acc2[p][j] = 0ull;

    // 5x5 on E
    #pragma unroll
    for (int u = 0; u < 5; u++) {
        float v[4][5];
        #pragma unroll
        for (int p = 0; p < 4; p++) {
            int base = (ty + 8*p + u)*36 + tx;
            #pragma unroll
            for (int j = 0; j < 5; j++) v[p][j] = sE[base + j];
        }
        #pragma unroll
        for (int vv = 0; vv < 5; vv++) {
            unsigned long long v2[4];
            #pragma unroll
            for (int p = 0; p < 4; p++) v2[p] = pack2(v[p][vv], v[p][vv]);
            const float4* w4 = (const float4*)&s_w5[(u*5 + vv)*16];
            #pragma unroll
            for (int q = 0; q < 4; q++) {
                float4 t4 = w4[q];
                unsigned long long wA = pack2(t4.x, t4.y), wB = pack2(t4.z, t4.w);
                #pragma unroll
                for (int p = 0; p < 4; p++) {
                    ffma2(acc2[p][q*2],   v2[p], wA);
                    ffma2(acc2[p][q*2+1], v2[p], wB);
                }
            }
        }
    }
    // 3x3 on x0,x1
    #pragma unroll
    for (int ch = 0; ch < 2; ch++)
        #pragma unroll
        for (int ky = 0; ky < 3; ky++) {
            float v[4][3];
            #pragma unroll
            for (int p = 0; p < 4; p++) {
                int base = (ty + 8*p + ky)*34 + tx;
                v[p][0] = sx[ch][base]; v[p][1] = sx[ch][base+1]; v[p][2] = sx[ch][base+2];
            }
            #pragma unroll
            for (int kx = 0; kx < 3; kx++) {
                unsigned long long v2[4];
                #pragma unroll
                for (int p = 0; p < 4; p++) v2[p] = pack2(v[p][kx], v[p][kx]);
                const float4* w4 = (const float4*)&s_w3[(ch*9 + ky*3 + kx)*16];
                #pragma unroll
                for (int q = 0; q < 4; q++) {
                    float4 t4 = w4[q];
                    unsigned long long wA = pack2(t4.x, t4.y), wB = pack2(t4.z, t4.w);
                    #pragma unroll
                    for (int p = 0; p < 4; p++) {
                        ffma2(acc2[p][q*2],   v2[p], wA);
                        ffma2(acc2[p][q*2+1], v2[p], wB);
                    }
                }
            }
        }

    #pragma unroll
    for (int p = 0; p < 4; p++) {
        int pp = p0 + ty + 8*p, qq = q0 + tx;
        if (pp <= 255 && qq <= 255) {
            float* op = &h1[(((long)b*48 + oc_base)*258 + pp)*258 + qq];
            #pragma unroll
            for (int j = 0; j < 8; j++) {
                float2 f = unpack2(acc2[p][j]);
                op[(long)(2*j  )*258*258] = ftanh(f.x);
                op[(long)(2*j+1)*258*258] = ftanh(f.y);
            }
        }
    }
}

// md_ct boundary (exact, scalar — tiny)
__global__ void k_mdct_edge(const float* __restrict__ x, const float* __restrict__ E,
                            const float* __restrict__ md_ct, float* __restrict__ h1) {
    __shared__ float s_w[4320];
    int tid = threadIdx.x;
    for (int i = tid; i < 4320; i += 256) {
        int oc = i % 48, rest = i / 48;
        s_w[rest*48 + oc] = md_ct[oc*90 + rest];
    }
    __syncthreads();
    int idx = blockIdx.x*256 + tid;
    int b = blockIdx.y;
    int p, q;
    if (idx < 1032) { int r = idx/258; p = (r < 2) ? r : 254 + r; q = idx - r*258; }
    else { int j = idx - 1032; int c = j/254; q = (c < 2) ? c : 254 + c; p = 2 + (j - c*254); }
    float acc[48];
    #pragma unroll
    for (int o = 0; o < 48; o++) acc[o] = 0.f;
    for (int ch = 0; ch < 10; ch++)
        for (int ky = 0; ky < 3; ky++)
            for (int kx = 0; kx < 3; kx++) {
                int y = p - 2 + ky, xx = q - 2 + kx;
                if ((unsigned)y < 256u && (unsigned)xx < 256u) {
                    float v;
                    if (ch < 2) v = x[((long)b*6 + ch)*HW + (y << 8) + xx];
                    else {
                        int k = ch - 2;
                        v = E[b*HW + (((y + c_dy[k]) & 255) << 8) + ((xx - c_dx[k]) & 255)];
                    }
                    const float* wr = &s_w[(ch*9 + ky*3 + kx)*48];
                    #pragma unroll
                    for (int o = 0; o < 48; o++) acc[o] = fmaf(v, wr[o], acc[o]);
                }
            }
    for (int o = 0; o < 48; o++)
        h1[(((long)b*48 + o)*258 + p)*258 + q] = ftanh(acc[o]);
}

// ---------------- direct 3x3 conv, packed FFMA2 over oc pairs ----------------
template<int CIN_G, int OCB, int PAD, bool DOTANH, bool SAFE, bool PREBN, bool REDUCE>
__global__ void __launch_bounds__(256, 2)
k_conv3(const float* __restrict__ in, const float* __restrict__ wgt,
        const float* __restrict__ sbp, float* __restrict__ out, float* __restrict__ red,
        int H_in, int W_in, int H_out, int W_out, int C_in, int C_out, int tilesX) {
    __shared__ float s_tile[34*34];
    __shared__ alignas(16) float s_w[CIN_G*9*OCB];
    __shared__ float s_sc[CIN_G], s_bi[CIN_G];
    __shared__ float s_rs[8][16], s_rq[8][16];

    int tid = threadIdx.x;
    int oc_base = blockIdx.x * OCB;
    int groups = C_in / CIN_G;
    int oc_per_group = C_out / groups;
    int ic_base = (oc_base / oc_per_group) * CIN_G;

    for (int i = tid; i < CIN_G*9*OCB; i += 256) {
        int o = i % OCB, rest = i / OCB;
        s_w[i] = wgt[(long)(oc_base + o)*(CIN_G*9) + rest];
    }
    if (PREBN && tid < CIN_G) { s_sc[tid] = sbp[ic_base + tid]; s_bi[tid] = sbp[48 + ic_base + tid]; }

    int tX = blockIdx.y % tilesX, tY = blockIdx.y / tilesX;
    int ox0 = tX*32, oy0 = tY*32;
    int tx = tid & 31, ty = tid >> 5;

    int off[5]; bool vld[5];
    #pragma unroll
    for (int s = 0; s < 5; s++) {
        int j = tid + s*256;
        int ly = j / 34, lx = j - ly*34;
        int gy = oy0 - PAD + ly, gx = ox0 - PAD + lx;
        bool v = (j < 1156);
        if (SAFE) v = v && ((unsigned)gy < (unsigned)H_in) && ((unsigned)gx < (unsigned)W_in);
        vld[s] = v;
        off[s] = gy*W_in + gx;
    }

    const float* inb = in + ((long)blockIdx.z * C_in + ic_base) * H_in * W_in;
    float r[5];
    #pragma unroll
    for (int s = 0; s < 5; s++) r[s] = vld[s] ? __ldg(inb + off[s]) : 0.f;

    unsigned long long acc2[4][OCB/2];
    #pragma unroll
    for (int p = 0; p < 4; p++)
        #pragma unroll
        for (int j = 0; j < OCB/2; j++) acc2[p][j] = 0ull;

    __syncthreads();

    #pragma unroll 1
    for (int ic = 0; ic < CIN_G; ic++) {
        float sc = 0.f, bi = 0.f;
        if (PREBN) { sc = s_sc[ic]; bi = s_bi[ic]; }
        #pragma unroll
        for (int s = 0; s < 5; s++) {
            int j = tid + s*256;
            if (j < 1156) {
                float v = r[s];
                if (PREBN) v = ftanh(fmaf(sc, v, bi));
                s_tile[j] = v;
            }
        }
        __syncthreads();
        if (ic + 1 < CIN_G) {
            const float* src = inb + (long)(ic+1)*H_in*W_in;
            #pragma unroll
            for (int s = 0; s < 5; s++) r[s] = vld[s] ? __ldg(src + off[s]) : 0.f;
        }
        const float* wic = &s_w[ic*9*OCB];
        #pragma unroll
        for (int ky = 0; ky < 3; ky++) {
            float v[4][3];
            #pragma unroll
            for (int p = 0; p < 4; p++) {
                int base = (ty + 8*p + ky)*34 + tx;
                v[p][0] = s_tile[base]; v[p][1] = s_tile[base+1]; v[p][2] = s_tile[base+2];
            }
            #pragma unroll
            for (int kx = 0; kx < 3; kx++) {
                unsigned long long v2[4];
                #pragma unroll
                for (int p = 0; p < 4; p++) v2[p] = pack2(v[p][kx], v[p][kx]);
                if (OCB % 4 == 0) {
                    const float4* w4 = (const float4*)&wic[(ky*3 + kx)*OCB];
                    #pragma unroll
                    for (int q = 0; q < OCB/4; q++) {
                        float4 t4 = w4[q];
                        unsigned long long wA = pack2(t4.x, t4.y), wB = pack2(t4.z, t4.w);
                        #pragma unroll
                        for (int p = 0; p < 4; p++) {
                            ffma2(acc2[p][q*2],   v2[p], wA);
                            ffma2(acc2[p][q*2+1], v2[p], wB);
                        }
                    }
                } else {
                    #pragma unroll
                    for (int j = 0; j < OCB/2; j++) {
                        unsigned long long ww =
                            *(const unsigned long long*)&wic[(ky*3 + kx)*OCB + 2*j];
                        #pragma unroll
                        for (int p = 0; p < 4; p++) ffma2(acc2[p][j], v2[p], ww);
                    }
                }
            }
        }
        __syncthreads();
    }

    float rs[REDUCE ? OCB : 1], rq[REDUCE ? OCB : 1];
    if (REDUCE) {
        #pragma unroll
        for (int o = 0; o < OCB; o++) { rs[o] = 0.f; rq[o] = 0.f; }
    }

    #pragma unroll
    for (int p = 0; p < 4; p++) {
        int oy = oy0 + ty + 8*p, ox = ox0 + tx;
        bool ok = (oy < H_out) && (ox < W_out);
        float* op = out + (((long)blockIdx.z*C_out + oc_base)*H_out + oy)*W_out + ox;
        long cs = (long)H_out*W_out;
        #pragma unroll
        for (int j = 0; j < OCB/2; j++) {
            float2 f = unpack2(acc2[p][j]);
            float v0 = DOTANH ? ftanh(f.x) : f.x;
            float v1 = DOTANH ? ftanh(f.y) : f.y;
            if (ok) { op[(2*j)*cs] = v0; op[(2*j+1)*cs] = v1; }
            if (REDUCE && ok) {
                rs[2*j]   += v0; rq[2*j]   += v0*v0;
                rs[2*j+1] += v1; rq[2*j+1] += v1*v1;
            }
        }
    }

    if (REDUCE) {
        int lane = tid & 31, warp = tid >> 5;
        #pragma unroll
        for (int o = 0; o < OCB; o++) {
            float s = rs[o], q = rq[o];
            #pragma unroll
            for (int d = 16; d > 0; d >>= 1) {
                s += __shfl_down_sync(0xffffffffu, s, d);
                q += __shfl_down_sync(0xffffffffu, q, d);
            }
            if (lane == 0) { s_rs[warp][o] = s; s_rq[warp][o] = q; }
        }
        __syncthreads();
        if (tid < OCB) {
            float S = 0.f, Q = 0.f;
            #pragma unroll
            for (int w8 = 0; w8 < 8; w8++) { S += s_rs[w8][tid]; Q += s_rq[w8][tid]; }
            atomicAdd(&red[oc_base + tid], S);
            atomicAdd(&red[C_out + oc_base + tid], Q);
        }
    }
}

// CHANGE = sigmoid(conv2x2s2(tanh(bn(h2)), md_c2))
__global__ void k_change(const float* __restrict__ h2, const float* __restrict__ sb,
                         const float* __restrict__ w2, float* __restrict__ ch) {
    __shared__ float s_s[48], s_b[48], s_w[192];
    int t = threadIdx.x;
    if (t < 48) { s_s[t] = sb[t]; s_b[t] = sb[48+t]; }
    if (t < 192) s_w[t] = w2[t];
    __syncthreads();
    int idx = blockIdx.x*256 + t;
    int b = idx >> 14, pix = idx & 16383;
    int i = pix >> 7, j = pix & 127;
    const float* hp0 = h2 + ((long)b*48)*HW + (2*i)*256 + 2*j;
    float a = 0.f;
    for (int c = 0; c < 48; c++) {
        const float* hp = hp0 + (long)c*HW;
        float s = s_s[c], bb = s_b[c];
        a = fmaf(ftanh(fmaf(s, hp[0],   bb)), s_w[c*4+0], a);
        a = fmaf(ftanh(fmaf(s, hp[1],   bb)), s_w[c*4+1], a);
        a = fmaf(ftanh(fmaf(s, hp[256], bb)), s_w[c*4+2], a);
        a = fmaf(ftanh(fmaf(s, hp[257], bb)), s_w[c*4+3], a);
    }
    ch[idx] = fsig(a);
}

__global__ void k_cm1red(const float* __restrict__ x, const float* __restrict__ w,
                         float* __restrict__ z, float* __restrict__ red) {
    __shared__ float ss[8], sq[8];
    int tid = threadIdx.x;
    int idx = blockIdx.x*256 + tid;
    int b = idx / (48*HW2); int r = idx - b*48*HW2;
    int oc = r >> 14; int pix = r & 16383;
    int i = pix >> 7, j = pix & 127;
    int g = oc >> 4;
    const float* xp = x + ((long)b*6 + 2*g)*HW + (2*i)*256 + 2*j;
    const float* wp = w + oc*8;
    float a = wp[0]*xp[0] + wp[1]*xp[1] + wp[2]*xp[256] + wp[3]*xp[257]
            + wp[4]*xp[HW] + wp[5]*xp[HW+1] + wp[6]*xp[HW+256] + wp[7]*xp[HW+257];
    z[idx] = a;
    float s = a, q = a*a;
    #pragma unroll
    for (int d = 16; d > 0; d >>= 1) {
        s += __shfl_down_sync(0xffffffffu, s, d);
        q += __shfl_down_sync(0xffffffffu, q, d);
    }
    int warp = tid >> 5, lane = tid & 31;
    if (lane == 0) { ss[warp] = s; sq[warp] = q; }
    __syncthreads();
    if (tid == 0) {
        float S = 0.f, Q = 0.f;
        #pragma unroll
        for (int w8 = 0; w8 < 8; w8++) { S += ss[w8]; Q += sq[w8]; }
        atomicAdd(&red[oc], S); atomicAdd(&red[48 + oc], Q);
    }
}

__global__ void k_final(const float* __restrict__ xm, const float* __restrict__ ch,
                        const float* __restrict__ w1, const float* __restrict__ w2,
                        const float* __restrict__ sb, float* __restrict__ out) {
    __shared__ float s_w1[288], s_w2[288], s_s[48], s_b[48];
    int t = threadIdx.x;
    for (int i = t; i < 288; i += 256) { s_w1[i] = w1[i]; s_w2[i] = w2[i]; }
    if (t < 48)  { s_s[t] = sb[t]; s_b[t] = sb[48+t]; }
    __syncthreads();
    int idx = blockIdx.x*256 + t;
    int b = idx >> 14, pix = idx & 16383;
    const float* xp = xm + ((long)b*6)*HW2 + pix;
    float v[6];
    #pragma unroll
    for (int d = 0; d < 6; d++) v[d] = xp[d*HW2];
    float born[6] = {0,0,0,0,0,0};
    #pragma unroll 4
    for (int c = 0; c < 48; c++) {
        float y = s_w1[c*6]*v[0];
        #pragma unroll
        for (int d = 1; d < 6; d++) y = fmaf(s_w1[c*6+d], v[d], y);
        float h = ftanh(fmaf(s_s[c], y, s_b[c]));
        #pragma unroll
        for (int d = 0; d < 6; d++) born[d] = fmaf(s_w2[d*48+c], h, born[d]);
    }
    float cc = ch[idx];
    #pragma unroll
    for (int d = 0; d < 6; d++) {
        float o = v[d]*(1.f - cc) + cc*born[d];
        if (d < 3) o = fsig(o);
        out[((long)b*6 + d)*HW2 + pix] = o;
    }
}

// ---------------- launch ----------------
extern "C" void kernel_launch(void* const* d_in, const int* in_sizes, int n_in,
                              void* d_out, int out_size) {
    const float* x     = (const float*)d_in[0];
    const float* ce_w1 = (const float*)d_in[1];
    const float* ce_g  = (const float*)d_in[2];
    const float* ce_b  = (const float*)d_in[3];
    const float* ce_w2 = (const float*)d_in[4];
    const float* md_ct = (const float*)d_in[5];
    const float* md_c1 = (const float*)d_in[6];
    const float* md_g  = (const float*)d_in[7];
    const float* md_b  = (const float*)d_in[8];
    const float* md_c2 = (const float*)d_in[9];
    const float* cm_w1 = (const float*)d_in[10];
    const float* cm_g  = (const float*)d_in[11];
    const float* cm_b  = (const float*)d_in[12];
    const float* cm_ct = (const float*)d_in[13];
    const float* cm_c2 = (const float*)d_in[14];
    const float* bo_w1 = (const float*)d_in[15];
    const float* bo_g  = (const float*)d_in[16];
    const float* bo_b  = (const float*)d_in[17];
    const float* bo_w2 = (const float*)d_in[18];

    float *E, *h1, *h2, *ch, *z, *hcm, *xm, *w5, *red, *sb;
    cudaGetSymbolAddress((void**)&E,   g_E);
    cudaGetSymbolAddress((void**)&h1,  g_h1);
    cudaGetSymbolAddress((void**)&h2,  g_h2);
    cudaGetSymbolAddress((void**)&ch,  g_ch);
    cudaGetSymbolAddress((void**)&z,   g_z);
    cudaGetSymbolAddress((void**)&hcm, g_hcm);
    cudaGetSymbolAddress((void**)&xm,  g_xm);
    cudaGetSymbolAddress((void**)&w5,  g_w5);
    cudaGetSymbolAddress((void**)&red, g_red);
    cudaGetSymbolAddress((void**)&sb,  g_sb);

    const float invN_full = 1.f/(float)(Bn*HW);
    const float invN_half = 1.f/(float)(Bn*HW2);

    k_zero<<<1, 512>>>(red);

    // ---- compenv ----
    k_mom6<<<64, 256>>>(x, red + 0, HW);
    k_sb6 <<<1, 64>>>(red + 0, ce_w1, ce_g, ce_b, sb + 0, invN_full);
    k_env <<<Bn*HW/256, 256>>>(x, ce_w1, ce_w2, sb + 0, E);

    // ---- merge change determinant ----
    k_w5<<<1, 64>>>(md_ct, w5);
    k_mdct<<<dim3(3, 64, Bn), 256>>>(x, E, w5, md_ct, h1);
    k_mdct_edge<<<dim3(8, Bn), 256>>>(x, E, md_ct, h1);
    k_conv3<48, 16, 0, true, false, false, true>
        <<<dim3(3, 64, Bn), 256>>>(h1, md_c1, nullptr, h2, red + 42,
                                   258, 258, 256, 256, 48, 48, 8);
    k_bnsb<<<1, 64>>>(red + 42, md_g, md_b, sb + 96, invN_full);
    k_change<<<Bn*HW2/256, 256>>>(h2, sb + 96, md_c2, ch);

    // ---- cell merge ----
    k_cm1red<<<Bn*48*HW2/256, 256>>>(x, cm_w1, z, red + 138);
    k_bnsb<<<1, 64>>>(red + 138, cm_g, cm_b, sb + 192, invN_half);
    k_conv3<16, 16, 2, true, true, true, false>
        <<<dim3(3, 25, Bn), 256>>>(z, cm_ct, sb + 192, hcm, nullptr,
                                   128, 128, 130, 130, 48, 48, 5);
    k_conv3<16, 2, 0, true, false, false, false>
        <<<dim3(3, 16, Bn), 256>>>(hcm, cm_c2, nullptr, xm, nullptr,
                                   130, 130, 128, 128, 48, 6, 4);

    // ---- born + blend ----
    k_mom6<<<64, 256>>>(xm, red + 234, HW2);
    k_sb6 <<<1, 64>>>(red + 234, bo_w1, bo_g, bo_b, sb + 288, invN_half);
    k_final<<<Bn*HW2/256, 256>>>(xm, ch, bo_w1, bo_w2, sb + 288, (float*)d_out);
}